// round 11
// baseline (speedup 1.0000x reference)
#include <cuda_runtime.h>
#include <cuda_bf16.h>
#include <cstdint>
#include <math.h>

#define BATCH   4
#define LSEQ    4096
#define M_TOTAL (BATCH * LSEQ)   // 16384
#define DM      1024
#define EE      2048             // E
#define N1      (2 * EE)         // 4096
#define DSTATE  16
#define DCONV   4

#define KP1 (3 * DM)             // 3072  split-K for GEMM1
#define KP2 (3 * EE)             // 6144  split-K for GEMM2

// -------- scratch (device globals: allocation-free rule) --------
__device__ float         g_xz[M_TOTAL * (size_t)N1];     // 256 MB (x_proj | z)
__device__ float         g_xconv[M_TOTAL * (size_t)EE];  // 128 MB
__device__ float         g_u[M_TOTAL * DSTATE];          // 1 MB
__device__ float         g_h[M_TOTAL * DSTATE];          // 1 MB
__device__ __nv_bfloat16 g_xs[M_TOTAL * (size_t)KP1];    // 96 MB  A' for GEMM1
__device__ __nv_bfloat16 g_w1[(size_t)N1 * KP1];         // 24 MB  B' for GEMM1
__device__ __nv_bfloat16 g_gs[M_TOTAL * (size_t)KP2];    // 192 MB A' for GEMM2
__device__ __nv_bfloat16 g_w2[(size_t)DM * KP2];         // 12 MB  B' for GEMM2

// ============================================================
// helpers
// ============================================================
__device__ __forceinline__ uint32_t smem_u32(const void* p) {
    uint32_t a;
    asm("{ .reg .u64 t; cvta.to.shared.u64 t, %1; cvt.u32.u64 %0, t; }"
        : "=r"(a) : "l"(p));
    return a;
}

#define CP_ASYNC_16(dst_u32, src_ptr) \
    asm volatile("cp.async.cg.shared.global [%0], [%1], 16;" \
                 :: "r"(dst_u32), "l"(src_ptr) : "memory")
#define CP_ASYNC_COMMIT() asm volatile("cp.async.commit_group;" ::: "memory")
#define CP_ASYNC_WAIT1()  asm volatile("cp.async.wait_group 1;" ::: "memory")

__device__ __forceinline__ void ldm_x4(uint32_t& r0, uint32_t& r1,
                                       uint32_t& r2, uint32_t& r3, uint32_t addr) {
    asm volatile("ldmatrix.sync.aligned.m8n8.x4.shared.b16 {%0,%1,%2,%3}, [%4];"
                 : "=r"(r0), "=r"(r1), "=r"(r2), "=r"(r3) : "r"(addr));
}
__device__ __forceinline__ void mma_bf16(float* d, const uint32_t* a,
                                         const uint32_t* b) {
    asm volatile(
        "mma.sync.aligned.m16n8k16.row.col.f32.bf16.bf16.f32 "
        "{%0,%1,%2,%3}, {%4,%5,%6,%7}, {%8,%9}, {%0,%1,%2,%3};"
        : "+f"(d[0]), "+f"(d[1]), "+f"(d[2]), "+f"(d[3])
        : "r"(a[0]), "r"(a[1]), "r"(a[2]), "r"(a[3]), "r"(b[0]), "r"(b[1]));
}

// ============================================================
// bf16 mma.sync GEMM: C[M,N] = A[M,KP] @ B[N,KP]^T + bias[N]
// 256x128 CTA tile, BK=64, 8 warps (warp tile 64m x 64n, 4x2),
// 3-stage cp.async pipeline (wait_group 1), 128B rows with XOR
// swizzle (conflict-free cp.async stores + ldmatrix loads).
// 4 MMAs per LDSM.x4 -> smem bandwidth no longer co-limiting.
// ============================================================
#define TBM 256
#define TBN 128
#define TBK 64
#define ROWB 128                             // bytes per smem row (64 bf16)
#define STAGE_A_BYTES (TBM * ROWB)           // 32768
#define STAGE_B_BYTES (TBN * ROWB)           // 16384
#define STAGE_BYTES   (STAGE_A_BYTES + STAGE_B_BYTES)  // 49152
#define NSTAGE 3
#define MM_SMEM_BYTES (NSTAGE * STAGE_BYTES) // 147456

__global__ __launch_bounds__(256, 1) void mm_gemm(
    const __nv_bfloat16* __restrict__ A,
    const __nv_bfloat16* __restrict__ B,
    const float* __restrict__ bias,
    float* __restrict__ C,
    int N, int KP)
{
    extern __shared__ char dynsmem[];
    const uint32_t sbase = smem_u32(dynsmem);

    const int tid = threadIdx.x;
    const int wid = tid >> 5;
    const int lane = tid & 31;
    const int bm = blockIdx.y * TBM;
    const int bn = blockIdx.x * TBN;

    const int wm = (wid & 3) * 64;   // warp m-offset (4 warps down M)
    const int wn = (wid >> 2) * 64;  // warp n-offset (2 warps across N)

    // ---- global->shared mapping
    // A: one full 128B row per thread (8 granules), rows 0..255
    const __nv_bfloat16* Agl = A + (size_t)(bm + tid) * KP;
    uint32_t adst[8];
#pragma unroll
    for (int g = 0; g < 8; g++)
        adst[g] = (uint32_t)(tid * ROWB) + (uint32_t)((g ^ (tid & 7)) << 4);
    // B: half row per thread (4 granules), rows 0..127
    const int brg = tid >> 1;
    const int bg0 = (tid & 1) * 4;
    const __nv_bfloat16* Bgl = B + (size_t)(bn + brg) * KP + bg0 * 8;
    uint32_t bdst[4];
#pragma unroll
    for (int i = 0; i < 4; i++)
        bdst[i] = (uint32_t)(brg * ROWB) + (uint32_t)(((bg0 + i) ^ (brg & 7)) << 4);

    uint32_t sA[NSTAGE], sB[NSTAGE];
#pragma unroll
    for (int s = 0; s < NSTAGE; s++) {
        sA[s] = sbase + s * STAGE_BYTES;
        sB[s] = sA[s] + STAGE_A_BYTES;
    }

    float acc[4][8][4];
#pragma unroll
    for (int i = 0; i < 4; i++)
#pragma unroll
        for (int j = 0; j < 8; j++)
#pragma unroll
            for (int k = 0; k < 4; k++) acc[i][j][k] = 0.f;

    // ---- ldmatrix per-thread bases
    // A x4: row = wm + mf*16 + (lane&15); granule = ks*2 + (lane>>4)
    const int arow = wm + (lane & 15);
    const int axor = arow & 7;                 // mf*16 keeps row&7 constant
    const int agl = lane >> 4;                 // 0/1
    // B x4 (two n-frags per ldsm): row = wn + nfp*16 + (lane&7) + ((lane>>4)<<3)
    const int brow = wn + (lane & 7) + ((lane >> 4) << 3);
    const int bxor = brow & 7;
    const int bgl = (lane >> 3) & 1;

    const int nchunk = KP / TBK;

    // prologue: prefetch stages 0..NSTAGE-2
#pragma unroll
    for (int s = 0; s < NSTAGE - 1; s++) {
        const size_t koff = (size_t)s * TBK;
#pragma unroll
        for (int g = 0; g < 8; g++)
            CP_ASYNC_16(sA[s] + adst[g], Agl + koff + g * 8);
#pragma unroll
        for (int i = 0; i < 4; i++)
            CP_ASYNC_16(sB[s] + bdst[i], Bgl + koff + i * 8);
        CP_ASYNC_COMMIT();
    }

    int buf = 0, nbuf = NSTAGE - 1;
    for (int c = 0; c < nchunk; c++) {
        CP_ASYNC_WAIT1();            // oldest group (chunk c) landed
        __syncthreads();

        if (c + NSTAGE - 1 < nchunk) {
            const size_t koff = (size_t)(c + NSTAGE - 1) * TBK;
#pragma unroll
            for (int g = 0; g < 8; g++)
                CP_ASYNC_16(sA[nbuf] + adst[g], Agl + koff + g * 8);
#pragma unroll
            for (int i = 0; i < 4; i++)
                CP_ASYNC_16(sB[nbuf] + bdst[i], Bgl + koff + i * 8);
        }
        CP_ASYNC_COMMIT();           // commit every iter to keep accounting

#pragma unroll
        for (int ks = 0; ks < 4; ks++) {
            uint32_t af[4][4], bfr[8][2];
#pragma unroll
            for (int mf = 0; mf < 4; mf++) {
                const int row = arow + mf * 16;
                const uint32_t addr =
                    sA[buf] + row * ROWB + (((ks * 2 + agl) ^ axor) << 4);
                ldm_x4(af[mf][0], af[mf][1], af[mf][2], af[mf][3], addr);
            }
#pragma unroll
            for (int nfp = 0; nfp < 4; nfp++) {
                const int row = brow + nfp * 16;
                const uint32_t addr =
                    sB[buf] + row * ROWB + (((ks * 2 + bgl) ^ bxor) << 4);
                ldm_x4(bfr[nfp * 2][0], bfr[nfp * 2][1],
                       bfr[nfp * 2 + 1][0], bfr[nfp * 2 + 1][1], addr);
            }
#pragma unroll
            for (int mf = 0; mf < 4; mf++)
#pragma unroll
                for (int nf = 0; nf < 8; nf++)
                    mma_bf16(acc[mf][nf], af[mf], bfr[nf]);
        }

        buf = (buf + 1 == NSTAGE) ? 0 : buf + 1;
        nbuf = (nbuf + 1 == NSTAGE) ? 0 : nbuf + 1;
    }

    // epilogue
    const int erow = bm + wm + (lane >> 2);
    const int ecol = bn + wn + (lane & 3) * 2;
#pragma unroll
    for (int mf = 0; mf < 4; mf++) {
#pragma unroll
        for (int nf = 0; nf < 8; nf++) {
            const int col = ecol + nf * 8;
            const float bx = bias[col], by = bias[col + 1];
            float* C0 = C + (size_t)(erow + mf * 16) * N + col;
            float* C1 = C0 + (size_t)8 * N;
            *(float2*)C0 = make_float2(acc[mf][nf][0] + bx, acc[mf][nf][1] + by);
            *(float2*)C1 = make_float2(acc[mf][nf][2] + bx, acc[mf][nf][3] + by);
        }
    }
}

// ============================================================
// Split x (fp32 [M,DM]) -> A' = [hi | hi | lo] bf16 [M, 3*DM]
// ============================================================
__global__ void split_x_kernel(const float* __restrict__ x,
                               __nv_bfloat16* __restrict__ xs)
{
    const int idx = blockIdx.x * 256 + threadIdx.x;  // over M_TOTAL*DM
    const int m = idx >> 10;
    const int k = idx & 1023;
    const float a = x[idx];
    const __nv_bfloat16 hi = __float2bfloat16(a);
    const float lo = a - __bfloat162float(hi);
    const size_t base = (size_t)m * KP1;
    xs[base + k] = hi;
    xs[base + DM + k] = hi;
    xs[base + 2 * DM + k] = __float2bfloat16(lo);
}

// ============================================================
// Transpose + split weights: W [K, N] fp32 -> B' [N, 3K] bf16 = [hi | lo | hi]
// ============================================================
__global__ __launch_bounds__(256) void wsplit_kernel(
    const float* __restrict__ W, __nv_bfloat16* __restrict__ Wt, int K, int N)
{
    __shared__ float t[32][33];
    const int k0 = blockIdx.y * 32;
    const int n0 = blockIdx.x * 32;
    const int tx = threadIdx.x & 31;
    const int ty = threadIdx.x >> 5;  // 0..7

    for (int i = ty; i < 32; i += 8)
        t[i][tx] = W[(size_t)(k0 + i) * N + n0 + tx];
    __syncthreads();

    for (int i = ty; i < 32; i += 8) {
        const int n = n0 + i;
        const int k = k0 + tx;
        const float a = t[tx][i];
        const __nv_bfloat16 hi = __float2bfloat16(a);
        const float lo = a - __bfloat162float(hi);
        const size_t base = (size_t)n * 3 * K;
        Wt[base + k] = hi;
        Wt[base + K + k] = __float2bfloat16(lo);
        Wt[base + 2 * K + k] = hi;
    }
}

// ============================================================
// Causal depthwise conv1d, k=4 (reads x_proj half of g_xz)
// ============================================================
__global__ void conv_kernel(const float* __restrict__ cw,
                            const float* __restrict__ cb,
                            float* __restrict__ xconv)
{
    const int idx = blockIdx.x * blockDim.x + threadIdx.x;
    const int e = idx & (EE - 1);
    const int m = idx >> 11;
    const int l = m & (LSEQ - 1);

    float acc = cb[e];
    const float w0 = cw[e * 4 + 0];
    const float w1 = cw[e * 4 + 1];
    const float w2 = cw[e * 4 + 2];
    const float w3 = cw[e * 4 + 3];
    if (l >= 3) acc += w0 * g_xz[(size_t)(m - 3) * N1 + e];
    if (l >= 2) acc += w1 * g_xz[(size_t)(m - 2) * N1 + e];
    if (l >= 1) acc += w2 * g_xz[(size_t)(m - 1) * N1 + e];
    acc += w3 * g_xz[(size_t)m * N1 + e];
    xconv[(size_t)m * EE + e] = acc;
}

// ============================================================
// u[m,s] = xconv[m,:] . A[:,s]
// ============================================================
__global__ void u_kernel(const float* __restrict__ Amat, float* __restrict__ u)
{
    const int m = blockIdx.x * 64 + (threadIdx.x >> 2);
    const int sg = (threadIdx.x & 3) * 4;
    const float* xr = g_xconv + (size_t)m * EE;

    float4 acc = make_float4(0.f, 0.f, 0.f, 0.f);
#pragma unroll 4
    for (int e = 0; e < EE; e += 4) {
        float4 xv = *(const float4*)(xr + e);
        float4 a0 = *(const float4*)(Amat + (e + 0) * DSTATE + sg);
        float4 a1 = *(const float4*)(Amat + (e + 1) * DSTATE + sg);
        float4 a2 = *(const float4*)(Amat + (e + 2) * DSTATE + sg);
        float4 a3 = *(const float4*)(Amat + (e + 3) * DSTATE + sg);
        acc.x += xv.x * a0.x + xv.y * a1.x + xv.z * a2.x + xv.w * a3.x;
        acc.y += xv.x * a0.y + xv.y * a1.y + xv.z * a2.y + xv.w * a3.y;
        acc.z += xv.x * a0.z + xv.y * a1.z + xv.z * a2.z + xv.w * a3.z;
        acc.w += xv.x * a0.w + xv.y * a1.w + xv.z * a2.w + xv.w * a3.w;
    }
    *(float4*)(u + (size_t)m * DSTATE + sg) = acc;
}

// ============================================================
// Sequential scan h_t = tanh(u_t + h_{t-1}), hardware tanh.approx,
// 16-deep load prefetch. 64 independent chains.
// ============================================================
__global__ void scan_kernel(const float* __restrict__ u, float* __restrict__ h)
{
    const int b = threadIdx.x >> 4;
    const int s = threadIdx.x & 15;
    const float* up = u + (size_t)b * LSEQ * DSTATE + s;
    float* hp = h + (size_t)b * LSEQ * DSTATE + s;

    float buf[16], nxt[16];
#pragma unroll
    for (int i = 0; i < 16; i++) buf[i] = __ldg(up + (size_t)i * DSTATE);

    float hv = 0.f;
    for (int l0 = 0; l0 < LSEQ; l0 += 16) {
        if (l0 + 16 < LSEQ) {
#pragma unroll
            for (int i = 0; i < 16; i++)
                nxt[i] = __ldg(up + (size_t)(l0 + 16 + i) * DSTATE);
        }
#pragma unroll
        for (int i = 0; i < 16; i++) {
            hv += buf[i];
            asm("tanh.approx.f32 %0, %0;" : "+f"(hv));
            hp[(size_t)(l0 + i) * DSTATE] = hv;
        }
#pragma unroll
        for (int i = 0; i < 16; i++) buf[i] = nxt[i];
    }
}

// ============================================================
// gated = sigmoid(z) * (h @ C^T + Dp * xconv) -> bf16 split triple
// G'[m] = [hi | hi | lo]  (A' for GEMM2)
// ============================================================
__global__ __launch_bounds__(256) void gated_kernel(
    const float* __restrict__ Cmat, const float* __restrict__ Dp,
    const float* __restrict__ h, __nv_bfloat16* __restrict__ gs)
{
    __shared__ float C_sh[256][17];
    __shared__ float h_sh[16][16];

    const int tid = threadIdx.x;
    const int e0 = blockIdx.x * 256;
    const int m0 = blockIdx.y * 16;

    {
        const float* crow = Cmat + (size_t)(e0 + tid) * DSTATE;
#pragma unroll
        for (int i = 0; i < DSTATE; i++) C_sh[tid][i] = crow[i];
    }
    ((float*)h_sh)[tid] = h[(size_t)m0 * DSTATE + tid];
    __syncthreads();

    const int e = e0 + tid;
    float creg[DSTATE];
#pragma unroll
    for (int i = 0; i < DSTATE; i++) creg[i] = C_sh[tid][i];
    const float dpe = Dp[e];

#pragma unroll
    for (int mi = 0; mi < 16; mi++) {
        const int m = m0 + mi;
        float dot = 0.f;
#pragma unroll
        for (int i = 0; i < DSTATE; i++) dot = fmaf(h_sh[mi][i], creg[i], dot);
        const float z = g_xz[(size_t)m * N1 + EE + e];
        const float xcv = g_xconv[(size_t)m * EE + e];
        const float sig = 1.f / (1.f + __expf(-z));
        const float val = sig * (dot + dpe * xcv);

        const __nv_bfloat16 hi = __float2bfloat16(val);
        const float lo = val - __bfloat162float(hi);
        const size_t base = (size_t)m * KP2;
        gs[base + e] = hi;
        gs[base + EE + e] = hi;
        gs[base + 2 * EE + e] = __float2bfloat16(lo);
    }
}

// ============================================================
extern "C" void kernel_launch(void* const* d_in, const int* in_sizes, int n_in,
                              void* d_out, int out_size)
{
    const float* x      = (const float*)d_in[0];
    const float* W_in   = (const float*)d_in[1];
    const float* b_in   = (const float*)d_in[2];
    const float* conv_w = (const float*)d_in[3];
    const float* conv_b = (const float*)d_in[4];
    const float* Amat   = (const float*)d_in[5];
    const float* Cmat   = (const float*)d_in[6];
    const float* Dp     = (const float*)d_in[7];
    const float* W_out  = (const float*)d_in[8];
    const float* b_out  = (const float*)d_in[9];
    float* out = (float*)d_out;

    float* xz    = nullptr; cudaGetSymbolAddress((void**)&xz,    g_xz);
    float* xconv = nullptr; cudaGetSymbolAddress((void**)&xconv, g_xconv);
    float* u     = nullptr; cudaGetSymbolAddress((void**)&u,     g_u);
    float* h     = nullptr; cudaGetSymbolAddress((void**)&h,     g_h);
    __nv_bfloat16* xs = nullptr; cudaGetSymbolAddress((void**)&xs, g_xs);
    __nv_bfloat16* w1 = nullptr; cudaGetSymbolAddress((void**)&w1, g_w1);
    __nv_bfloat16* gs = nullptr; cudaGetSymbolAddress((void**)&gs, g_gs);
    __nv_bfloat16* w2 = nullptr; cudaGetSymbolAddress((void**)&w2, g_w2);

    cudaFuncSetAttribute(mm_gemm, cudaFuncAttributeMaxDynamicSharedMemorySize,
                         MM_SMEM_BYTES);

    // 0) splits
    split_x_kernel<<<(M_TOTAL * DM) / 256, 256>>>(x, xs);
    {
        dim3 g1(N1 / 32, DM / 32);
        wsplit_kernel<<<g1, 256>>>(W_in, w1, DM, N1);
        dim3 g2(DM / 32, EE / 32);
        wsplit_kernel<<<g2, 256>>>(W_out, w2, EE, DM);
    }

    // 1) xz = x @ W_in + b_in  (bf16-split mma.sync GEMM, K' = 3072)
    {
        dim3 grid(N1 / TBN, M_TOTAL / TBM);
        mm_gemm<<<grid, 256, MM_SMEM_BYTES>>>(xs, w1, b_in, xz, N1, KP1);
    }

    // 2) causal depthwise conv
    conv_kernel<<<(M_TOTAL * EE) / 256, 256>>>(conv_w, conv_b, xconv);

    // 3) u = xconv @ A
    u_kernel<<<M_TOTAL / 64, 256>>>(Amat, u);

    // 4) sequential tanh scan
    scan_kernel<<<1, BATCH * DSTATE>>>(u, h);

    // 5) gated (writes bf16 split triple directly)
    {
        dim3 grid(EE / 256, M_TOTAL / 16);
        gated_kernel<<<grid, 256>>>(Cmat, Dp, h, gs);
    }

    // 6) out = gated @ W_out + b_out  (K' = 6144)
    {
        dim3 grid(DM / TBN, M_TOTAL / TBM);
        mm_gemm<<<grid, 256, MM_SMEM_BYTES>>>(gs, w2, b_out, out, DM, KP2);
    }
}

// round 13
// speedup vs baseline: 2.6063x; 2.6063x over previous
#include <cuda_runtime.h>
#include <cuda_fp16.h>
#include <cstdint>
#include <math.h>

#define BATCH   4
#define LSEQ    4096
#define M_TOTAL (BATCH * LSEQ)   // 16384
#define DM      1024
#define EE      2048             // E
#define N1      (2 * EE)         // 4096
#define DSTATE  16
#define DCONV   4

#define KP1 DM                   // 1024  fp16 single-pass GEMM1
#define KP2 EE                   // 2048  fp16 single-pass GEMM2

// -------- scratch (device globals: allocation-free rule) --------
__device__ float  g_xz[M_TOTAL * (size_t)N1];     // 256 MB (x_proj | z)
__device__ float  g_xconv[M_TOTAL * (size_t)EE];  // 128 MB
__device__ float  g_u[M_TOTAL * DSTATE];          // 1 MB
__device__ float  g_h[M_TOTAL * DSTATE];          // 1 MB
__device__ __half g_xs[M_TOTAL * (size_t)KP1];    // 32 MB  A for GEMM1
__device__ __half g_w1[(size_t)N1 * KP1];         // 8 MB   B for GEMM1
__device__ __half g_gs[M_TOTAL * (size_t)KP2];    // 64 MB  A for GEMM2
__device__ __half g_w2[(size_t)DM * KP2];         // 4 MB   B for GEMM2

// ============================================================
// helpers
// ============================================================
__device__ __forceinline__ uint32_t smem_u32(const void* p) {
    uint32_t a;
    asm("{ .reg .u64 t; cvta.to.shared.u64 t, %1; cvt.u32.u64 %0, t; }"
        : "=r"(a) : "l"(p));
    return a;
}

#define CP_ASYNC_16(dst_u32, src_ptr) \
    asm volatile("cp.async.cg.shared.global [%0], [%1], 16;" \
                 :: "r"(dst_u32), "l"(src_ptr) : "memory")
#define CP_ASYNC_COMMIT() asm volatile("cp.async.commit_group;" ::: "memory")
#define CP_ASYNC_WAIT1()  asm volatile("cp.async.wait_group 1;" ::: "memory")

__device__ __forceinline__ void ldm_x4(uint32_t& r0, uint32_t& r1,
                                       uint32_t& r2, uint32_t& r3, uint32_t addr) {
    asm volatile("ldmatrix.sync.aligned.m8n8.x4.shared.b16 {%0,%1,%2,%3}, [%4];"
                 : "=r"(r0), "=r"(r1), "=r"(r2), "=r"(r3) : "r"(addr));
}
__device__ __forceinline__ void mma_f16(float* d, const uint32_t* a,
                                        const uint32_t* b) {
    asm volatile(
        "mma.sync.aligned.m16n8k16.row.col.f32.f16.f16.f32 "
        "{%0,%1,%2,%3}, {%4,%5,%6,%7}, {%8,%9}, {%0,%1,%2,%3};"
        : "+f"(d[0]), "+f"(d[1]), "+f"(d[2]), "+f"(d[3])
        : "r"(a[0]), "r"(a[1]), "r"(a[2]), "r"(a[3]), "r"(b[0]), "r"(b[1]));
}

// ============================================================
// fp16 mma.sync GEMM: C[M,N] = A[M,KP] @ B[N,KP]^T + bias[N]
// 128x128 CTA tile, BK=64, 8 warps (warp tile 64m x 32n),
// 3-stage cp.async pipeline (wait_group 1), 128B rows with XOR
// swizzle (conflict-free cp.async stores + ldmatrix loads).
// (Best-measured R10 configuration, fp16 operands.)
// ============================================================
#define TBM 128
#define TBN 128
#define TBK 64
#define ROWB 128                             // bytes per smem row (64 fp16)
#define STAGE_A_BYTES (TBM * ROWB)           // 16384
#define STAGE_BYTES   (2 * STAGE_A_BYTES)    // 32768 (A then B)
#define NSTAGE 3
#define MM_SMEM_BYTES (NSTAGE * STAGE_BYTES) // 98304

// swizzled byte offset for (row, 16B-granule g) in a 128B-row tile
__device__ __forceinline__ uint32_t swz(int row, int g) {
    return (uint32_t)(row * ROWB) + (uint32_t)((g ^ (row & 7)) << 4);
}

__global__ __launch_bounds__(256, 2) void mm_gemm(
    const __half* __restrict__ A,
    const __half* __restrict__ B,
    const float* __restrict__ bias,
    float* __restrict__ C,
    int N, int KP)
{
    extern __shared__ char dynsmem[];
    const uint32_t sbase = smem_u32(dynsmem);

    const int tid = threadIdx.x;
    const int wid = tid >> 5;
    const int lane = tid & 31;
    const int bm = blockIdx.y * TBM;
    const int bn = blockIdx.x * TBN;

    const int wm = (wid & 1) * 64;   // warp m-offset in tile
    const int wn = (wid >> 1) * 32;  // warp n-offset in tile

    // ---- global->shared mapping: thread t covers row = t>>1,
    //      granules (t&1)*4 .. +3 (half a 128B row)
    const int grow = tid >> 1;             // 0..127
    const int gg0 = (tid & 1) * 4;         // 0 or 4
    const __half* Agl = A + (size_t)(bm + grow) * KP + gg0 * 8;
    const __half* Bgl = B + (size_t)(bn + grow) * KP + gg0 * 8;
    uint32_t gdst[4];
#pragma unroll
    for (int i = 0; i < 4; i++) gdst[i] = swz(grow, gg0 + i);

    uint32_t sA[NSTAGE], sB[NSTAGE];
#pragma unroll
    for (int s = 0; s < NSTAGE; s++) {
        sA[s] = sbase + s * STAGE_BYTES;
        sB[s] = sA[s] + STAGE_A_BYTES;
    }

    float acc[4][4][4];
#pragma unroll
    for (int i = 0; i < 4; i++)
#pragma unroll
        for (int j = 0; j < 4; j++)
#pragma unroll
            for (int k = 0; k < 4; k++) acc[i][j][k] = 0.f;

    // ---- ldmatrix per-thread bases
    const int arow = wm + (lane & 15);
    const int axor = arow & 7;                 // mf*16 keeps row&7 constant
    const int agl = lane >> 4;                 // 0/1
    const int brow = wn + (lane & 7) + ((lane >> 4) << 3);
    const int bxor = brow & 7;
    const int bgl = (lane >> 3) & 1;

    const int nchunk = KP / TBK;               // 16 or 32

    // prologue: prefetch stages 0..NSTAGE-2
#pragma unroll
    for (int s = 0; s < NSTAGE - 1; s++) {
        const size_t koff = (size_t)s * TBK;
#pragma unroll
        for (int i = 0; i < 4; i++) {
            CP_ASYNC_16(sA[s] + gdst[i], Agl + koff + i * 8);
            CP_ASYNC_16(sB[s] + gdst[i], Bgl + koff + i * 8);
        }
        CP_ASYNC_COMMIT();
    }

    int buf = 0, nbuf = NSTAGE - 1;
    for (int c = 0; c < nchunk; c++) {
        CP_ASYNC_WAIT1();            // oldest group (chunk c) landed
        __syncthreads();

        if (c + NSTAGE - 1 < nchunk) {
            const size_t koff = (size_t)(c + NSTAGE - 1) * TBK;
#pragma unroll
            for (int i = 0; i < 4; i++) {
                CP_ASYNC_16(sA[nbuf] + gdst[i], Agl + koff + i * 8);
                CP_ASYNC_16(sB[nbuf] + gdst[i], Bgl + koff + i * 8);
            }
        }
        CP_ASYNC_COMMIT();           // commit every iter to keep accounting

#pragma unroll
        for (int ks = 0; ks < 4; ks++) {
            uint32_t af[4][4], bfr[4][2];
#pragma unroll
            for (int mf = 0; mf < 4; mf++) {
                const int row = arow + mf * 16;
                const uint32_t addr =
                    sA[buf] + row * ROWB + (((ks * 2 + agl) ^ axor) << 4);
                ldm_x4(af[mf][0], af[mf][1], af[mf][2], af[mf][3], addr);
            }
#pragma unroll
            for (int nfp = 0; nfp < 2; nfp++) {
                const int row = brow + nfp * 16;
                const uint32_t addr =
                    sB[buf] + row * ROWB + (((ks * 2 + bgl) ^ bxor) << 4);
                ldm_x4(bfr[nfp * 2][0], bfr[nfp * 2][1],
                       bfr[nfp * 2 + 1][0], bfr[nfp * 2 + 1][1], addr);
            }
#pragma unroll
            for (int mf = 0; mf < 4; mf++)
#pragma unroll
                for (int nf = 0; nf < 4; nf++)
                    mma_f16(acc[mf][nf], af[mf], bfr[nf]);
        }

        buf = (buf + 1 == NSTAGE) ? 0 : buf + 1;
        nbuf = (nbuf + 1 == NSTAGE) ? 0 : nbuf + 1;
    }

    // epilogue
    const int erow = bm + wm + (lane >> 2);
    const int ecol = bn + wn + (lane & 3) * 2;
#pragma unroll
    for (int mf = 0; mf < 4; mf++) {
#pragma unroll
        for (int nf = 0; nf < 4; nf++) {
            const int col = ecol + nf * 8;
            const float bx = bias[col], by = bias[col + 1];
            float* C0 = C + (size_t)(erow + mf * 16) * N + col;
            float* C1 = C0 + (size_t)8 * N;
            *(float2*)C0 = make_float2(acc[mf][nf][0] + bx, acc[mf][nf][1] + by);
            *(float2*)C1 = make_float2(acc[mf][nf][2] + bx, acc[mf][nf][3] + by);
        }
    }
}

// ============================================================
// Cast x (fp32 [M,DM]) -> fp16 [M,DM] (contiguous)
// ============================================================
__global__ void cast_x_kernel(const float* __restrict__ x,
                              __half* __restrict__ xs)
{
    const int idx = blockIdx.x * 256 + threadIdx.x;  // over M_TOTAL*DM/4
    const float4 v = ((const float4*)x)[idx];
    __half2* o = (__half2*)xs + idx * 2;
    o[0] = __floats2half2_rn(v.x, v.y);
    o[1] = __floats2half2_rn(v.z, v.w);
}

// ============================================================
// Transpose weights: W [K, N] fp32 -> Wt [N, K] fp16
// ============================================================
__global__ __launch_bounds__(256) void wtrans_kernel(
    const float* __restrict__ W, __half* __restrict__ Wt, int K, int N)
{
    __shared__ float t[32][33];
    const int k0 = blockIdx.y * 32;
    const int n0 = blockIdx.x * 32;
    const int tx = threadIdx.x & 31;
    const int ty = threadIdx.x >> 5;  // 0..7

    for (int i = ty; i < 32; i += 8)
        t[i][tx] = W[(size_t)(k0 + i) * N + n0 + tx];
    __syncthreads();

    for (int i = ty; i < 32; i += 8)
        Wt[(size_t)(n0 + i) * K + k0 + tx] = __float2half(t[tx][i]);
}

// ============================================================
// Causal depthwise conv1d, k=4 (reads x_proj half of g_xz)
// ============================================================
__global__ void conv_kernel(const float* __restrict__ cw,
                            const float* __restrict__ cb,
                            float* __restrict__ xconv)
{
    const int idx = blockIdx.x * blockDim.x + threadIdx.x;
    const int e = idx & (EE - 1);
    const int m = idx >> 11;
    const int l = m & (LSEQ - 1);

    float acc = cb[e];
    const float w0 = cw[e * 4 + 0];
    const float w1 = cw[e * 4 + 1];
    const float w2 = cw[e * 4 + 2];
    const float w3 = cw[e * 4 + 3];
    if (l >= 3) acc += w0 * g_xz[(size_t)(m - 3) * N1 + e];
    if (l >= 2) acc += w1 * g_xz[(size_t)(m - 2) * N1 + e];
    if (l >= 1) acc += w2 * g_xz[(size_t)(m - 1) * N1 + e];
    acc += w3 * g_xz[(size_t)m * N1 + e];
    xconv[(size_t)m * EE + e] = acc;
}

// ============================================================
// u[m,s] = xconv[m,:] . A[:,s]
// ============================================================
__global__ void u_kernel(const float* __restrict__ Amat, float* __restrict__ u)
{
    const int m = blockIdx.x * 64 + (threadIdx.x >> 2);
    const int sg = (threadIdx.x & 3) * 4;
    const float* xr = g_xconv + (size_t)m * EE;

    float4 acc = make_float4(0.f, 0.f, 0.f, 0.f);
#pragma unroll 4
    for (int e = 0; e < EE; e += 4) {
        float4 xv = *(const float4*)(xr + e);
        float4 a0 = *(const float4*)(Amat + (e + 0) * DSTATE + sg);
        float4 a1 = *(const float4*)(Amat + (e + 1) * DSTATE + sg);
        float4 a2 = *(const float4*)(Amat + (e + 2) * DSTATE + sg);
        float4 a3 = *(const float4*)(Amat + (e + 3) * DSTATE + sg);
        acc.x += xv.x * a0.x + xv.y * a1.x + xv.z * a2.x + xv.w * a3.x;
        acc.y += xv.x * a0.y + xv.y * a1.y + xv.z * a2.y + xv.w * a3.y;
        acc.z += xv.x * a0.z + xv.y * a1.z + xv.z * a2.z + xv.w * a3.z;
        acc.w += xv.x * a0.w + xv.y * a1.w + xv.z * a2.w + xv.w * a3.w;
    }
    *(float4*)(u + (size_t)m * DSTATE + sg) = acc;
}

// ============================================================
// Sequential scan h_t = tanh(u_t + h_{t-1}), hardware tanh.approx,
// 16-deep load prefetch. 64 independent chains.
// ============================================================
__global__ void scan_kernel(const float* __restrict__ u, float* __restrict__ h)
{
    const int b = threadIdx.x >> 4;
    const int s = threadIdx.x & 15;
    const float* up = u + (size_t)b * LSEQ * DSTATE + s;
    float* hp = h + (size_t)b * LSEQ * DSTATE + s;

    float buf[16], nxt[16];
#pragma unroll
    for (int i = 0; i < 16; i++) buf[i] = __ldg(up + (size_t)i * DSTATE);

    float hv = 0.f;
    for (int l0 = 0; l0 < LSEQ; l0 += 16) {
        if (l0 + 16 < LSEQ) {
#pragma unroll
            for (int i = 0; i < 16; i++)
                nxt[i] = __ldg(up + (size_t)(l0 + 16 + i) * DSTATE);
        }
#pragma unroll
        for (int i = 0; i < 16; i++) {
            hv += buf[i];
            asm("tanh.approx.f32 %0, %0;" : "+f"(hv));
            hp[(size_t)(l0 + i) * DSTATE] = hv;
        }
#pragma unroll
        for (int i = 0; i < 16; i++) buf[i] = nxt[i];
    }
}

// ============================================================
// gated = sigmoid(z) * (h @ C^T + Dp * xconv) -> fp16 [M, EE]
// ============================================================
__global__ __launch_bounds__(256) void gated_kernel(
    const float* __restrict__ Cmat, const float* __restrict__ Dp,
    const float* __restrict__ h, __half* __restrict__ gs)
{
    __shared__ float C_sh[256][17];
    __shared__ float h_sh[16][16];

    const int tid = threadIdx.x;
    const int e0 = blockIdx.x * 256;
    const int m0 = blockIdx.y * 16;

    {
        const float* crow = Cmat + (size_t)(e0 + tid) * DSTATE;
#pragma unroll
        for (int i = 0; i < DSTATE; i++) C_sh[tid][i] = crow[i];
    }
    ((float*)h_sh)[tid] = h[(size_t)m0 * DSTATE + tid];
    __syncthreads();

    const int e = e0 + tid;
    float creg[DSTATE];
#pragma unroll
    for (int i = 0; i < DSTATE; i++) creg[i] = C_sh[tid][i];
    const float dpe = Dp[e];

#pragma unroll
    for (int mi = 0; mi < 16; mi++) {
        const int m = m0 + mi;
        float dot = 0.f;
#pragma unroll
        for (int i = 0; i < DSTATE; i++) dot = fmaf(h_sh[mi][i], creg[i], dot);
        const float z = g_xz[(size_t)m * N1 + EE + e];
        const float xcv = g_xconv[(size_t)m * EE + e];
        const float sig = 1.f / (1.f + __expf(-z));
        gs[(size_t)m * EE + e] = __float2half(sig * (dot + dpe * xcv));
    }
}

// ============================================================
extern "C" void kernel_launch(void* const* d_in, const int* in_sizes, int n_in,
                              void* d_out, int out_size)
{
    const float* x      = (const float*)d_in[0];
    const float* W_in   = (const float*)d_in[1];
    const float* b_in   = (const float*)d_in[2];
    const float* conv_w = (const float*)d_in[3];
    const float* conv_b = (const float*)d_in[4];
    const float* Amat   = (const float*)d_in[5];
    const float* Cmat   = (const float*)d_in[6];
    const float* Dp     = (const float*)d_in[7];
    const float* W_out  = (const float*)d_in[8];
    const float* b_out  = (const float*)d_in[9];
    float* out = (float*)d_out;

    float* xz    = nullptr; cudaGetSymbolAddress((void**)&xz,    g_xz);
    float* xconv = nullptr; cudaGetSymbolAddress((void**)&xconv, g_xconv);
    float* u     = nullptr; cudaGetSymbolAddress((void**)&u,     g_u);
    float* h     = nullptr; cudaGetSymbolAddress((void**)&h,     g_h);
    __half* xs = nullptr; cudaGetSymbolAddress((void**)&xs, g_xs);
    __half* w1 = nullptr; cudaGetSymbolAddress((void**)&w1, g_w1);
    __half* gs = nullptr; cudaGetSymbolAddress((void**)&gs, g_gs);
    __half* w2 = nullptr; cudaGetSymbolAddress((void**)&w2, g_w2);

    cudaFuncSetAttribute(mm_gemm, cudaFuncAttributeMaxDynamicSharedMemorySize,
                         MM_SMEM_BYTES);

    // 0) casts / transposes
    cast_x_kernel<<<(M_TOTAL * DM / 4) / 256, 256>>>(x, xs);
    {
        dim3 g1(N1 / 32, DM / 32);
        wtrans_kernel<<<g1, 256>>>(W_in, w1, DM, N1);
        dim3 g2(DM / 32, EE / 32);
        wtrans_kernel<<<g2, 256>>>(W_out, w2, EE, DM);
    }

    // 1) xz = x @ W_in + b_in  (fp16 mma.sync GEMM, K = 1024)
    {
        dim3 grid(N1 / TBN, M_TOTAL / TBM);
        mm_gemm<<<grid, 256, MM_SMEM_BYTES>>>(xs, w1, b_in, xz, N1, KP1);
    }

    // 2) causal depthwise conv
    conv_kernel<<<(M_TOTAL * EE) / 256, 256>>>(conv_w, conv_b, xconv);

    // 3) u = xconv @ A
    u_kernel<<<M_TOTAL / 64, 256>>>(Amat, u);

    // 4) sequential tanh scan
    scan_kernel<<<1, BATCH * DSTATE>>>(u, h);

    // 5) gated (writes fp16 directly)
    {
        dim3 grid(EE / 256, M_TOTAL / 16);
        gated_kernel<<<grid, 256>>>(Cmat, Dp, h, gs);
    }

    // 6) out = gated @ W_out + b_out  (fp16, K = 2048)
    {
        dim3 grid(DM / TBN, M_TOTAL / TBM);
        mm_gemm<<<grid, 256, MM_SMEM_BYTES>>>(gs, w2, b_out, out, DM, KP2);
    }
}

// round 14
// speedup vs baseline: 2.8874x; 1.1079x over previous
#include <cuda_runtime.h>
#include <cuda_fp16.h>
#include <cstdint>
#include <math.h>

#define BATCH   4
#define LSEQ    4096
#define M_TOTAL (BATCH * LSEQ)   // 16384
#define DM      1024
#define EE      2048             // E
#define N1      (2 * EE)         // 4096
#define DSTATE  16
#define DCONV   4

#define KP1 DM                   // 1024  fp16 single-pass GEMM1
#define KP2 EE                   // 2048  fp16 single-pass GEMM2

// -------- scratch (device globals: allocation-free rule) --------
__device__ float  g_xp[M_TOTAL * (size_t)EE];     // 128 MB  x_proj
__device__ float  g_zp[M_TOTAL * (size_t)EE];     // 128 MB  z
__device__ float  g_xconv[M_TOTAL * (size_t)EE];  // 128 MB
__device__ float  g_u[M_TOTAL * DSTATE];          // 1 MB
__device__ float  g_h[M_TOTAL * DSTATE];          // 1 MB
__device__ __half g_xs[M_TOTAL * (size_t)KP1];    // 32 MB  A for GEMM1
__device__ __half g_w1[(size_t)N1 * KP1];         // 8 MB   B for GEMM1
__device__ __half g_gs[M_TOTAL * (size_t)KP2];    // 64 MB  A for GEMM2
__device__ __half g_w2[(size_t)DM * KP2];         // 4 MB   B for GEMM2

// ============================================================
// helpers
// ============================================================
__device__ __forceinline__ uint32_t smem_u32(const void* p) {
    uint32_t a;
    asm("{ .reg .u64 t; cvta.to.shared.u64 t, %1; cvt.u32.u64 %0, t; }"
        : "=r"(a) : "l"(p));
    return a;
}

#define CP_ASYNC_16(dst_u32, src_ptr) \
    asm volatile("cp.async.cg.shared.global [%0], [%1], 16;" \
                 :: "r"(dst_u32), "l"(src_ptr) : "memory")
#define CP_ASYNC_COMMIT() asm volatile("cp.async.commit_group;" ::: "memory")
#define CP_ASYNC_WAIT1()  asm volatile("cp.async.wait_group 1;" ::: "memory")

__device__ __forceinline__ void ldm_x4(uint32_t& r0, uint32_t& r1,
                                       uint32_t& r2, uint32_t& r3, uint32_t addr) {
    asm volatile("ldmatrix.sync.aligned.m8n8.x4.shared.b16 {%0,%1,%2,%3}, [%4];"
                 : "=r"(r0), "=r"(r1), "=r"(r2), "=r"(r3) : "r"(addr));
}
__device__ __forceinline__ void mma_f16(float* d, const uint32_t* a,
                                        const uint32_t* b) {
    asm volatile(
        "mma.sync.aligned.m16n8k16.row.col.f32.f16.f16.f32 "
        "{%0,%1,%2,%3}, {%4,%5,%6,%7}, {%8,%9}, {%0,%1,%2,%3};"
        : "+f"(d[0]), "+f"(d[1]), "+f"(d[2]), "+f"(d[3])
        : "r"(a[0]), "r"(a[1]), "r"(a[2]), "r"(a[3]), "r"(b[0]), "r"(b[1]));
}

// ============================================================
// fp16 mma.sync GEMM: C = A[M,KP] @ B[N,KP]^T + bias[N]
// 128x128 CTA tile, BK=64, 8 warps (warp tile 64m x 32n),
// 3-stage cp.async pipeline, XOR-swizzled 128B rows.
// mode 0: C[M,N] fp32 (stride N)
// mode 1: cols < EE -> C (stride EE); cols >= EE -> C2 (stride EE)
// ============================================================
#define TBM 128
#define TBN 128
#define TBK 64
#define ROWB 128                             // bytes per smem row (64 fp16)
#define STAGE_A_BYTES (TBM * ROWB)           // 16384
#define STAGE_BYTES   (2 * STAGE_A_BYTES)    // 32768 (A then B)
#define NSTAGE 3
#define MM_SMEM_BYTES (NSTAGE * STAGE_BYTES) // 98304

__device__ __forceinline__ uint32_t swz(int row, int g) {
    return (uint32_t)(row * ROWB) + (uint32_t)((g ^ (row & 7)) << 4);
}

__global__ __launch_bounds__(256, 2) void mm_gemm(
    const __half* __restrict__ A,
    const __half* __restrict__ B,
    const float* __restrict__ bias,
    float* __restrict__ C,
    float* __restrict__ C2,
    int N, int KP, int mode)
{
    extern __shared__ char dynsmem[];
    const uint32_t sbase = smem_u32(dynsmem);

    const int tid = threadIdx.x;
    const int wid = tid >> 5;
    const int lane = tid & 31;
    const int bm = blockIdx.y * TBM;
    const int bn = blockIdx.x * TBN;

    const int wm = (wid & 1) * 64;   // warp m-offset in tile
    const int wn = (wid >> 1) * 32;  // warp n-offset in tile

    // ---- global->shared mapping
    const int grow = tid >> 1;             // 0..127
    const int gg0 = (tid & 1) * 4;         // 0 or 4
    const __half* Agl = A + (size_t)(bm + grow) * KP + gg0 * 8;
    const __half* Bgl = B + (size_t)(bn + grow) * KP + gg0 * 8;
    uint32_t gdst[4];
#pragma unroll
    for (int i = 0; i < 4; i++) gdst[i] = swz(grow, gg0 + i);

    uint32_t sA[NSTAGE], sB[NSTAGE];
#pragma unroll
    for (int s = 0; s < NSTAGE; s++) {
        sA[s] = sbase + s * STAGE_BYTES;
        sB[s] = sA[s] + STAGE_A_BYTES;
    }

    float acc[4][4][4];
#pragma unroll
    for (int i = 0; i < 4; i++)
#pragma unroll
        for (int j = 0; j < 4; j++)
#pragma unroll
            for (int k = 0; k < 4; k++) acc[i][j][k] = 0.f;

    // ---- ldmatrix per-thread bases
    const int arow = wm + (lane & 15);
    const int axor = arow & 7;
    const int agl = lane >> 4;
    const int brow = wn + (lane & 7) + ((lane >> 4) << 3);
    const int bxor = brow & 7;
    const int bgl = (lane >> 3) & 1;

    const int nchunk = KP / TBK;

    // prologue
#pragma unroll
    for (int s = 0; s < NSTAGE - 1; s++) {
        const size_t koff = (size_t)s * TBK;
#pragma unroll
        for (int i = 0; i < 4; i++) {
            CP_ASYNC_16(sA[s] + gdst[i], Agl + koff + i * 8);
            CP_ASYNC_16(sB[s] + gdst[i], Bgl + koff + i * 8);
        }
        CP_ASYNC_COMMIT();
    }

    int buf = 0, nbuf = NSTAGE - 1;
    for (int c = 0; c < nchunk; c++) {
        CP_ASYNC_WAIT1();
        __syncthreads();

        if (c + NSTAGE - 1 < nchunk) {
            const size_t koff = (size_t)(c + NSTAGE - 1) * TBK;
#pragma unroll
            for (int i = 0; i < 4; i++) {
                CP_ASYNC_16(sA[nbuf] + gdst[i], Agl + koff + i * 8);
                CP_ASYNC_16(sB[nbuf] + gdst[i], Bgl + koff + i * 8);
            }
        }
        CP_ASYNC_COMMIT();

#pragma unroll
        for (int ks = 0; ks < 4; ks++) {
            uint32_t af[4][4], bfr[4][2];
#pragma unroll
            for (int mf = 0; mf < 4; mf++) {
                const int row = arow + mf * 16;
                const uint32_t addr =
                    sA[buf] + row * ROWB + (((ks * 2 + agl) ^ axor) << 4);
                ldm_x4(af[mf][0], af[mf][1], af[mf][2], af[mf][3], addr);
            }
#pragma unroll
            for (int nfp = 0; nfp < 2; nfp++) {
                const int row = brow + nfp * 16;
                const uint32_t addr =
                    sB[buf] + row * ROWB + (((ks * 2 + bgl) ^ bxor) << 4);
                ldm_x4(bfr[nfp * 2][0], bfr[nfp * 2][1],
                       bfr[nfp * 2 + 1][0], bfr[nfp * 2 + 1][1], addr);
            }
#pragma unroll
            for (int mf = 0; mf < 4; mf++)
#pragma unroll
                for (int nf = 0; nf < 4; nf++)
                    mma_f16(acc[mf][nf], af[mf], bfr[nf]);
        }

        buf = (buf + 1 == NSTAGE) ? 0 : buf + 1;
        nbuf = (nbuf + 1 == NSTAGE) ? 0 : nbuf + 1;
    }

    // epilogue: resolve destination (uniform per block)
    float* Cb = C;
    int S = N, coff = 0;
    if (mode == 1) {
        S = EE;
        if (bn >= EE) { Cb = C2; coff = EE; }
    }
    const int erow = bm + wm + (lane >> 2);
    const int ecol = bn + wn + (lane & 3) * 2;
#pragma unroll
    for (int mf = 0; mf < 4; mf++) {
#pragma unroll
        for (int nf = 0; nf < 4; nf++) {
            const int col = ecol + nf * 8;
            const float bx = bias[col], by = bias[col + 1];
            float* C0 = Cb + (size_t)(erow + mf * 16) * S + (col - coff);
            float* C1 = C0 + (size_t)8 * S;
            *(float2*)C0 = make_float2(acc[mf][nf][0] + bx, acc[mf][nf][1] + by);
            *(float2*)C1 = make_float2(acc[mf][nf][2] + bx, acc[mf][nf][3] + by);
        }
    }
}

// ============================================================
// Cast x (fp32 [M,DM]) -> fp16 [M,DM] (contiguous)
// ============================================================
__global__ void cast_x_kernel(const float* __restrict__ x,
                              __half* __restrict__ xs)
{
    const int idx = blockIdx.x * 256 + threadIdx.x;  // over M_TOTAL*DM/4
    const float4 v = ((const float4*)x)[idx];
    __half2* o = (__half2*)xs + idx * 2;
    o[0] = __floats2half2_rn(v.x, v.y);
    o[1] = __floats2half2_rn(v.z, v.w);
}

// ============================================================
// Transpose weights: W [K, N] fp32 -> Wt [N, K] fp16
// ============================================================
__global__ __launch_bounds__(256) void wtrans_kernel(
    const float* __restrict__ W, __half* __restrict__ Wt, int K, int N)
{
    __shared__ float t[32][33];
    const int k0 = blockIdx.y * 32;
    const int n0 = blockIdx.x * 32;
    const int tx = threadIdx.x & 31;
    const int ty = threadIdx.x >> 5;  // 0..7

    for (int i = ty; i < 32; i += 8)
        t[i][tx] = W[(size_t)(k0 + i) * N + n0 + tx];
    __syncthreads();

    for (int i = ty; i < 32; i += 8)
        Wt[(size_t)(n0 + i) * K + k0 + tx] = __float2half(t[tx][i]);
}

// ============================================================
// Causal depthwise conv1d, k=4 — tiled 32 rows x 512 cols,
// register rolling window: ~1.09x read amplification.
// ============================================================
#define CBM 32
#define CBE 512

__global__ __launch_bounds__(256) void conv_kernel(
    const float* __restrict__ cw, const float* __restrict__ cb,
    const float* __restrict__ xp, float* __restrict__ xconv)
{
    const int t = threadIdx.x;
    const int c4 = t & 127;              // float4 column within e-tile
    const int rg = t >> 7;               // row group 0/1 (16 rows each)
    const int e0 = blockIdx.x * CBE + c4 * 4;
    const int m0 = blockIdx.y * CBM + rg * 16;
    const int l0 = m0 & (LSEQ - 1);

    // per-e weights: w[tap][j] for e0+j
    float w[4][4];
#pragma unroll
    for (int j = 0; j < 4; j++) {
        const float4 we = *(const float4*)(cw + (size_t)(e0 + j) * 4);
        w[0][j] = we.x; w[1][j] = we.y; w[2][j] = we.z; w[3][j] = we.w;
    }
    const float4 bias4 = *(const float4*)(cb + e0);

    const float* xrow = xp + (size_t)m0 * EE + e0;
    float* orow = xconv + (size_t)m0 * EE + e0;

    float4 xm3, xm2, xm1;
    if (l0 == 0) {
        xm3 = xm2 = xm1 = make_float4(0.f, 0.f, 0.f, 0.f);
    } else {    // l0 >= 16 here, so all three prev rows are in-batch
        xm3 = *(const float4*)(xrow - (size_t)3 * EE);
        xm2 = *(const float4*)(xrow - (size_t)2 * EE);
        xm1 = *(const float4*)(xrow - (size_t)1 * EE);
    }

#pragma unroll
    for (int r = 0; r < 16; r++) {
        const float4 cur = *(const float4*)(xrow + (size_t)r * EE);
        float4 o;
        o.x = bias4.x + w[0][0]*xm3.x + w[1][0]*xm2.x + w[2][0]*xm1.x + w[3][0]*cur.x;
        o.y = bias4.y + w[0][1]*xm3.y + w[1][1]*xm2.y + w[2][1]*xm1.y + w[3][1]*cur.y;
        o.z = bias4.z + w[0][2]*xm3.z + w[1][2]*xm2.z + w[2][2]*xm1.z + w[3][2]*cur.z;
        o.w = bias4.w + w[0][3]*xm3.w + w[1][3]*xm2.w + w[2][3]*xm1.w + w[3][3]*cur.w;
        *(float4*)(orow + (size_t)r * EE) = o;
        xm3 = xm2; xm2 = xm1; xm1 = cur;
    }
}

// ============================================================
// u[m,s] = xconv[m,:] . A[:,s]
// ============================================================
__global__ void u_kernel(const float* __restrict__ Amat, float* __restrict__ u)
{
    const int m = blockIdx.x * 64 + (threadIdx.x >> 2);
    const int sg = (threadIdx.x & 3) * 4;
    const float* xr = g_xconv + (size_t)m * EE;

    float4 acc = make_float4(0.f, 0.f, 0.f, 0.f);
#pragma unroll 4
    for (int e = 0; e < EE; e += 4) {
        float4 xv = *(const float4*)(xr + e);
        float4 a0 = *(const float4*)(Amat + (e + 0) * DSTATE + sg);
        float4 a1 = *(const float4*)(Amat + (e + 1) * DSTATE + sg);
        float4 a2 = *(const float4*)(Amat + (e + 2) * DSTATE + sg);
        float4 a3 = *(const float4*)(Amat + (e + 3) * DSTATE + sg);
        acc.x += xv.x * a0.x + xv.y * a1.x + xv.z * a2.x + xv.w * a3.x;
        acc.y += xv.x * a0.y + xv.y * a1.y + xv.z * a2.y + xv.w * a3.y;
        acc.z += xv.x * a0.z + xv.y * a1.z + xv.z * a2.z + xv.w * a3.z;
        acc.w += xv.x * a0.w + xv.y * a1.w + xv.z * a2.w + xv.w * a3.w;
    }
    *(float4*)(u + (size_t)m * DSTATE + sg) = acc;
}

// ============================================================
// Sequential scan h_t = tanh(u_t + h_{t-1}), hardware tanh.approx,
// 16-deep load prefetch. 64 independent chains.
// ============================================================
__global__ void scan_kernel(const float* __restrict__ u, float* __restrict__ h)
{
    const int b = threadIdx.x >> 4;
    const int s = threadIdx.x & 15;
    const float* up = u + (size_t)b * LSEQ * DSTATE + s;
    float* hp = h + (size_t)b * LSEQ * DSTATE + s;

    float buf[16], nxt[16];
#pragma unroll
    for (int i = 0; i < 16; i++) buf[i] = __ldg(up + (size_t)i * DSTATE);

    float hv = 0.f;
    for (int l0 = 0; l0 < LSEQ; l0 += 16) {
        if (l0 + 16 < LSEQ) {
#pragma unroll
            for (int i = 0; i < 16; i++)
                nxt[i] = __ldg(up + (size_t)(l0 + 16 + i) * DSTATE);
        }
#pragma unroll
        for (int i = 0; i < 16; i++) {
            hv += buf[i];
            asm("tanh.approx.f32 %0, %0;" : "+f"(hv));
            hp[(size_t)(l0 + i) * DSTATE] = hv;
        }
#pragma unroll
        for (int i = 0; i < 16; i++) buf[i] = nxt[i];
    }
}

// ============================================================
// gated = sigmoid(z) * (h @ C^T + Dp * xconv) -> fp16 [M, EE]
// ============================================================
__global__ __launch_bounds__(256) void gated_kernel(
    const float* __restrict__ Cmat, const float* __restrict__ Dp,
    const float* __restrict__ h, __half* __restrict__ gs)
{
    __shared__ float C_sh[256][17];
    __shared__ float h_sh[16][16];

    const int tid = threadIdx.x;
    const int e0 = blockIdx.x * 256;
    const int m0 = blockIdx.y * 16;

    {
        const float* crow = Cmat + (size_t)(e0 + tid) * DSTATE;
#pragma unroll
        for (int i = 0; i < DSTATE; i++) C_sh[tid][i] = crow[i];
    }
    ((float*)h_sh)[tid] = h[(size_t)m0 * DSTATE + tid];
    __syncthreads();

    const int e = e0 + tid;
    float creg[DSTATE];
#pragma unroll
    for (int i = 0; i < DSTATE; i++) creg[i] = C_sh[tid][i];
    const float dpe = Dp[e];

#pragma unroll
    for (int mi = 0; mi < 16; mi++) {
        const int m = m0 + mi;
        float dot = 0.f;
#pragma unroll
        for (int i = 0; i < DSTATE; i++) dot = fmaf(h_sh[mi][i], creg[i], dot);
        const float z = g_zp[(size_t)m * EE + e];
        const float xcv = g_xconv[(size_t)m * EE + e];
        const float sig = 1.f / (1.f + __expf(-z));
        gs[(size_t)m * EE + e] = __float2half(sig * (dot + dpe * xcv));
    }
}

// ============================================================
extern "C" void kernel_launch(void* const* d_in, const int* in_sizes, int n_in,
                              void* d_out, int out_size)
{
    const float* x      = (const float*)d_in[0];
    const float* W_in   = (const float*)d_in[1];
    const float* b_in   = (const float*)d_in[2];
    const float* conv_w = (const float*)d_in[3];
    const float* conv_b = (const float*)d_in[4];
    const float* Amat   = (const float*)d_in[5];
    const float* Cmat   = (const float*)d_in[6];
    const float* Dp     = (const float*)d_in[7];
    const float* W_out  = (const float*)d_in[8];
    const float* b_out  = (const float*)d_in[9];
    float* out = (float*)d_out;

    float* xp    = nullptr; cudaGetSymbolAddress((void**)&xp,    g_xp);
    float* zp    = nullptr; cudaGetSymbolAddress((void**)&zp,    g_zp);
    float* xconv = nullptr; cudaGetSymbolAddress((void**)&xconv, g_xconv);
    float* u     = nullptr; cudaGetSymbolAddress((void**)&u,     g_u);
    float* h     = nullptr; cudaGetSymbolAddress((void**)&h,     g_h);
    __half* xs = nullptr; cudaGetSymbolAddress((void**)&xs, g_xs);
    __half* w1 = nullptr; cudaGetSymbolAddress((void**)&w1, g_w1);
    __half* gs = nullptr; cudaGetSymbolAddress((void**)&gs, g_gs);
    __half* w2 = nullptr; cudaGetSymbolAddress((void**)&w2, g_w2);

    cudaFuncSetAttribute(mm_gemm, cudaFuncAttributeMaxDynamicSharedMemorySize,
                         MM_SMEM_BYTES);

    // 0) casts / transposes
    cast_x_kernel<<<(M_TOTAL * DM / 4) / 256, 256>>>(x, xs);
    {
        dim3 g1(N1 / 32, DM / 32);
        wtrans_kernel<<<g1, 256>>>(W_in, w1, DM, N1);
        dim3 g2(DM / 32, EE / 32);
        wtrans_kernel<<<g2, 256>>>(W_out, w2, EE, DM);
    }

    // 1) [x_proj | z] = x @ W_in + b_in  (fp16 GEMM, split epilogue)
    {
        dim3 grid(N1 / TBN, M_TOTAL / TBM);
        mm_gemm<<<grid, 256, MM_SMEM_BYTES>>>(xs, w1, b_in, xp, zp,
                                              N1, KP1, 1);
    }

    // 2) causal depthwise conv (tiled, rolling window)
    {
        dim3 grid(EE / CBE, M_TOTAL / CBM);
        conv_kernel<<<grid, 256>>>(conv_w, conv_b, xp, xconv);
    }

    // 3) u = xconv @ A
    u_kernel<<<M_TOTAL / 64, 256>>>(Amat, u);

    // 4) sequential tanh scan
    scan_kernel<<<1, BATCH * DSTATE>>>(u, h);

    // 5) gated (writes fp16 directly)
    {
        dim3 grid(EE / 256, M_TOTAL / 16);
        gated_kernel<<<grid, 256>>>(Cmat, Dp, h, gs);
    }

    // 6) out = gated @ W_out + b_out  (fp16, K = 2048)
    {
        dim3 grid(DM / TBN, M_TOTAL / TBM);
        mm_gemm<<<grid, 256, MM_SMEM_BYTES>>>(gs, w2, b_out, out, nullptr,
                                              DM, KP2, 0);
    }
}